// round 1
// baseline (speedup 1.0000x reference)
#include <cuda_runtime.h>

// LSTM autoencoder: enc (F=32 -> H=64), dec (H=64 -> F=32), B=512, T=1024.
// Persistent-style: 128 blocks x 256 threads, 4 batch rows per block.
// Batch rows are independent across time -> no cross-block sync ever.
// Weights live in SMEM (padded rows, conflict-free LDS.128), c-state in regs,
// h exchanged via SMEM with 4 barriers/step. FMA work uses packed fma.rn.f32x2.

#define T_STEPS 1024
#define FDIM    32
#define HDIM    64
#define GE      256   // 4*H enc gates
#define GD      128   // 4*F dec gates
#define KC      96    // concat input length for both LSTMs
#define WP      100   // padded weight/vec row (100 % 32 == 4 -> conflict-free)
#define ROWS    4
#define NBLK    128
#define NTHR    256

// shared memory float offsets
#define OFF_ENCW 0
#define OFF_DECW (OFF_ENCW + GE * WP)          // 25600
#define OFF_XHE  (OFF_DECW + GD * WP)          // 38400  [4][100]: x(32) | h_enc(64)
#define OFF_XHD  (OFF_XHE + ROWS * WP)         // 38800  [4][100]: h_enc(64) | h_dec(32)
#define GEP      260
#define OFF_GE   (OFF_XHD + ROWS * WP)         // 39200  [4][260] enc gate preacts
#define GDP      132
#define OFF_GD   (OFF_GE + ROWS * GEP)         // 40240  [4][132] dec gate preacts
#define OFF_BE   (OFF_GD + ROWS * GDP)         // 40768  [256] enc bias
#define OFF_BD   (OFF_BE + GE)                 // 41024  [128] dec bias
#define SMEM_FLOATS (OFF_BD + GD)              // 41152 floats = 164608 bytes

typedef unsigned long long ull;

union U64F2 { ull u; float2 f; };

__device__ __forceinline__ ull ffma2(ull a, ull b, ull c) {
    ull d;
    asm("fma.rn.f32x2 %0, %1, %2, %3;" : "=l"(d) : "l"(a), "l"(b), "l"(c));
    return d;
}

__device__ __forceinline__ float hsum2(ull a) {
    U64F2 u; u.u = a;
    return u.f.x + u.f.y;
}

__device__ __forceinline__ float sigf(float x) {
    // 1 / (1 + e^-x); __expf -> MUFU.EX2, __fdividef -> MUFU.RCP. No NaN paths.
    return __fdividef(1.0f, 1.0f + __expf(-x));
}

__device__ __forceinline__ float tanh_fast(float x) {
    // tanh(x) = 1 - 2/(e^{2x} + 1); saturates cleanly at +-1, no inf/inf NaN.
    float e = __expf(2.0f * x);
    return 1.0f - __fdividef(2.0f, e + 1.0f);
}

__global__ void __launch_bounds__(NTHR, 1) lstm_ae_kernel(
    const float* __restrict__ x,
    const float* __restrict__ ew_ih, const float* __restrict__ ew_hh,
    const float* __restrict__ eb_ih, const float* __restrict__ eb_hh,
    const float* __restrict__ dw_ih, const float* __restrict__ dw_hh,
    const float* __restrict__ db_ih, const float* __restrict__ db_hh,
    float* __restrict__ out)
{
    extern __shared__ float sm[];
    const int tid = threadIdx.x;
    const int b0  = blockIdx.x * ROWS;

    // ---- load weights into SMEM: concat [w_ih | w_hh] per gate, padded to WP ----
    for (int i = tid; i < GE * KC; i += NTHR) {
        int g = i / KC, k = i % KC;
        float v = (k < FDIM) ? ew_ih[g * FDIM + k] : ew_hh[g * HDIM + (k - FDIM)];
        sm[OFF_ENCW + g * WP + k] = v;
    }
    for (int i = tid; i < GD * KC; i += NTHR) {
        int g = i / KC, k = i % KC;
        float v = (k < HDIM) ? dw_ih[g * HDIM + k] : dw_hh[g * FDIM + (k - HDIM)];
        sm[OFF_DECW + g * WP + k] = v;
    }
    for (int i = tid; i < GE; i += NTHR) sm[OFF_BE + i] = eb_ih[i] + eb_hh[i];
    for (int i = tid; i < GD; i += NTHR) sm[OFF_BD + i] = db_ih[i] + db_hh[i];

    // zero xh buffers (XHE and XHD are contiguous: 2*ROWS*WP floats)
    for (int i = tid; i < 2 * ROWS * WP; i += NTHR) sm[OFF_XHE + i] = 0.0f;
    __syncthreads();

    // x(t=0) into xh_enc
    if (tid < ROWS * FDIM) {
        int row = tid >> 5, xj = tid & 31;
        sm[OFF_XHE + row * WP + xj] =
            x[((size_t)(b0 + row) * T_STEPS + 0) * FDIM + xj];
    }

    float c_enc = 0.0f;
    float c_dec = 0.0f;

    // x prefetch pipeline (threads 128..255 own one (row, feature) each)
    const int prow = (tid - 128) >> 5;
    const int pxj  = (tid - 128) & 31;
    float x_pref = 0.0f;
    if (tid >= 128)
        x_pref = x[((size_t)(b0 + prow) * T_STEPS + 1) * FDIM + pxj];

    // FMA-phase lane decomposition: lane = (row r in [0,4)) * 8 + (gq in [0,8))
    const int lane = tid & 31;
    const int wrp  = tid >> 5;
    const int r    = lane >> 3;
    const int gq   = lane & 7;
    const int gbE  = wrp * 32 + gq;   // enc: 4 gates, stride 8
    const int gbD  = wrp * 16 + gq;   // dec: 2 gates, stride 8

    const float* xhE = sm + OFF_XHE + r * WP;
    const float* xhD = sm + OFF_XHD + r * WP;
    const float* wE  = sm + OFF_ENCW + gbE * WP;
    const float* wD  = sm + OFF_DECW + gbD * WP;

    // elementwise-phase decompositions
    const int erow = tid >> 6, ej = tid & 63;   // enc: 4 rows x 64
    const int drow = tid >> 5, dj = tid & 31;   // dec: 4 rows x 32 (tid < 128)

    __syncthreads();

    for (int t = 0; t < T_STEPS; ++t) {
        // ---- phase 1: encoder gate pre-activations ----
        {
            ull a0 = 0ull, a1 = 0ull, a2 = 0ull, a3 = 0ull;
            #pragma unroll
            for (int kc = 0; kc < KC / 4; ++kc) {
                ulonglong2 hv = *reinterpret_cast<const ulonglong2*>(xhE + kc * 4);
                ulonglong2 w0 = *reinterpret_cast<const ulonglong2*>(wE + 0 * 8 * WP + kc * 4);
                ulonglong2 w1 = *reinterpret_cast<const ulonglong2*>(wE + 1 * 8 * WP + kc * 4);
                ulonglong2 w2 = *reinterpret_cast<const ulonglong2*>(wE + 2 * 8 * WP + kc * 4);
                ulonglong2 w3 = *reinterpret_cast<const ulonglong2*>(wE + 3 * 8 * WP + kc * 4);
                a0 = ffma2(w0.x, hv.x, a0); a0 = ffma2(w0.y, hv.y, a0);
                a1 = ffma2(w1.x, hv.x, a1); a1 = ffma2(w1.y, hv.y, a1);
                a2 = ffma2(w2.x, hv.x, a2); a2 = ffma2(w2.y, hv.y, a2);
                a3 = ffma2(w3.x, hv.x, a3); a3 = ffma2(w3.y, hv.y, a3);
            }
            float* ge = sm + OFF_GE + r * GEP + gbE;
            ge[0]  = hsum2(a0);
            ge[8]  = hsum2(a1);
            ge[16] = hsum2(a2);
            ge[24] = hsum2(a3);
        }
        __syncthreads();

        // ---- phase 2: encoder elementwise (c in regs), h -> SMEM; x prefetch ----
        {
            const float* ge = sm + OFF_GE + erow * GEP;
            float gi = ge[ej]        + sm[OFF_BE + ej];
            float gf = ge[64 + ej]   + sm[OFF_BE + 64 + ej];
            float gg = ge[128 + ej]  + sm[OFF_BE + 128 + ej];
            float go = ge[192 + ej]  + sm[OFF_BE + 192 + ej];
            float iv = sigf(gi), fv = sigf(gf);
            float gv = tanh_fast(gg), ov = sigf(go);
            c_enc = fv * c_enc + iv * gv;
            float h = ov * tanh_fast(c_enc);
            sm[OFF_XHE + erow * WP + FDIM + ej] = h;  // enc recurrence input
            sm[OFF_XHD + erow * WP + ej]        = h;  // dec input
        }
        if (tid >= 128) {
            if (t + 1 < T_STEPS)
                sm[OFF_XHE + prow * WP + pxj] = x_pref;
            if (t + 2 < T_STEPS)
                x_pref = x[((size_t)(b0 + prow) * T_STEPS + (t + 2)) * FDIM + pxj];
        }
        __syncthreads();

        // ---- phase 3: decoder gate pre-activations ----
        {
            ull d0 = 0ull, d1 = 0ull;
            #pragma unroll
            for (int kc = 0; kc < KC / 4; ++kc) {
                ulonglong2 hv = *reinterpret_cast<const ulonglong2*>(xhD + kc * 4);
                ulonglong2 w0 = *reinterpret_cast<const ulonglong2*>(wD + 0 * 8 * WP + kc * 4);
                ulonglong2 w1 = *reinterpret_cast<const ulonglong2*>(wD + 1 * 8 * WP + kc * 4);
                d0 = ffma2(w0.x, hv.x, d0); d0 = ffma2(w0.y, hv.y, d0);
                d1 = ffma2(w1.x, hv.x, d1); d1 = ffma2(w1.y, hv.y, d1);
            }
            float* gd = sm + OFF_GD + r * GDP + gbD;
            gd[0] = hsum2(d0);
            gd[8] = hsum2(d1);
        }
        __syncthreads();

        // ---- phase 4: decoder elementwise + output store ----
        if (tid < 128) {
            const float* gd = sm + OFF_GD + drow * GDP;
            float gi = gd[dj]       + sm[OFF_BD + dj];
            float gf = gd[32 + dj]  + sm[OFF_BD + 32 + dj];
            float gg = gd[64 + dj]  + sm[OFF_BD + 64 + dj];
            float go = gd[96 + dj]  + sm[OFF_BD + 96 + dj];
            float iv = sigf(gi), fv = sigf(gf);
            float gv = tanh_fast(gg), ov = sigf(go);
            c_dec = fv * c_dec + iv * gv;
            float h = ov * tanh_fast(c_dec);
            sm[OFF_XHD + drow * WP + HDIM + dj] = h;  // dec recurrence input
            out[((size_t)(b0 + drow) * T_STEPS + t) * FDIM + dj] = h;
        }
        __syncthreads();
    }
}

extern "C" void kernel_launch(void* const* d_in, const int* in_sizes, int n_in,
                              void* d_out, int out_size)
{
    (void)in_sizes; (void)n_in; (void)out_size;
    cudaFuncSetAttribute(lstm_ae_kernel,
                         cudaFuncAttributeMaxDynamicSharedMemorySize,
                         SMEM_FLOATS * (int)sizeof(float));
    lstm_ae_kernel<<<NBLK, NTHR, SMEM_FLOATS * sizeof(float)>>>(
        (const float*)d_in[0],
        (const float*)d_in[1], (const float*)d_in[2],
        (const float*)d_in[3], (const float*)d_in[4],
        (const float*)d_in[5], (const float*)d_in[6],
        (const float*)d_in[7], (const float*)d_in[8],
        (float*)d_out);
}

// round 2
// speedup vs baseline: 2.0552x; 2.0552x over previous
#include <cuda_runtime.h>

// LSTM autoencoder, weights-in-registers version.
// enc (F=32 -> H=64), dec (H=64 -> F=32), B=512, T=1024.
// 128 blocks x 256 threads, 4 batch rows per block, one wave on 148 SMs.
// Thread (q = tid&3, e = tid>>2) owns k-quarter [24q, 24q+24) of:
//   enc gates {e, e+64, e+128, e+192}  (unit e's i,f,g,o)
//   dec gates {e, e+64}
// -> 144 weight floats per thread held in 72 packed 64-bit regs (fma.rn.f32x2).
// SMEM holds only the h/x vectors (broadcast reads) + 4-partial exchange arrays.
// Decoder is pipelined one step behind the encoder: one FMA phase computes
// enc(t) and dec(t-1) gates together -> 2 barriers per step.

#define T_STEPS 1024
#define FDIM    32
#define HDIM    64
#define ROWS    4
#define NBLK    128
#define NTHR    256
#define XHP     104   // padded xh row stride (floats), 16B-aligned

// shared memory float offsets
#define OFF_XHE 0                        // [4][104]: x(32) | h_enc(64)
#define OFF_XHD (ROWS * XHP)             // 416: [4][104]: h_enc(64) | h_dec(32)
#define OFF_PE  (2 * ROWS * XHP)         // 832: [4][256][4] enc gate partials
#define OFF_PD  (OFF_PE + ROWS * 256 * 4) // 4928: [4][128][4] dec gate partials
#define SMEMN   (OFF_PD + ROWS * 128 * 4) // 6976 floats = 27904 B

typedef unsigned long long ull;
union U64F2 { ull u; float2 f; };

__device__ __forceinline__ ull pk(float lo, float hi) {
    U64F2 u; u.f = make_float2(lo, hi); return u.u;
}
__device__ __forceinline__ ull ffma2(ull a, ull b, ull c) {
    ull d;
    asm("fma.rn.f32x2 %0, %1, %2, %3;" : "=l"(d) : "l"(a), "l"(b), "l"(c));
    return d;
}
__device__ __forceinline__ float hsum2(ull a) {
    U64F2 u; u.u = a; return u.f.x + u.f.y;
}
__device__ __forceinline__ float sigf(float x) {
    return __fdividef(1.0f, 1.0f + __expf(-x));
}
__device__ __forceinline__ float tanh_fast(float x) {
    float e = __expf(2.0f * x);
    return 1.0f - __fdividef(2.0f, e + 1.0f);
}
__device__ __forceinline__ float sum4(float4 p) {
    return (p.x + p.y) + (p.z + p.w);
}

__global__ void __launch_bounds__(NTHR, 1) lstm_ae_kernel(
    const float* __restrict__ x,
    const float* __restrict__ ew_ih, const float* __restrict__ ew_hh,
    const float* __restrict__ eb_ih, const float* __restrict__ eb_hh,
    const float* __restrict__ dw_ih, const float* __restrict__ dw_hh,
    const float* __restrict__ db_ih, const float* __restrict__ db_hh,
    float* __restrict__ out)
{
    __shared__ __align__(16) float sm[SMEMN];
    const int tid = threadIdx.x;
    const int b0  = blockIdx.x * ROWS;
    const int q   = tid & 3;
    const int e   = tid >> 2;          // [0, 64)
    const int k0b = 24 * q;

    // ---- weights -> registers (one-time, mostly L2 hits) ----
    ull wE[4][12], wD[2][12];
    #pragma unroll
    for (int gi = 0; gi < 4; ++gi) {
        const int g = e + 64 * gi;
        #pragma unroll
        for (int j = 0; j < 12; ++j) {
            const int k0 = k0b + 2 * j, k1 = k0 + 1;
            float lo = (k0 < FDIM) ? ew_ih[g * FDIM + k0] : ew_hh[g * HDIM + (k0 - FDIM)];
            float hi = (k1 < FDIM) ? ew_ih[g * FDIM + k1] : ew_hh[g * HDIM + (k1 - FDIM)];
            wE[gi][j] = pk(lo, hi);
        }
    }
    #pragma unroll
    for (int di = 0; di < 2; ++di) {
        const int g = e + 64 * di;
        #pragma unroll
        for (int j = 0; j < 12; ++j) {
            const int k0 = k0b + 2 * j, k1 = k0 + 1;
            float lo = (k0 < HDIM) ? dw_ih[g * HDIM + k0] : dw_hh[g * FDIM + (k0 - HDIM)];
            float hi = (k1 < HDIM) ? dw_ih[g * HDIM + k1] : dw_hh[g * FDIM + (k1 - HDIM)];
            wD[di][j] = pk(lo, hi);
        }
    }

    // ---- per-thread biases for the elementwise phases ----
    const int er = tid >> 6, ej = tid & 63;   // enc elementwise: (row, unit)
    const float bE0 = eb_ih[ej]       + eb_hh[ej];
    const float bE1 = eb_ih[ej + 64]  + eb_hh[ej + 64];
    const float bE2 = eb_ih[ej + 128] + eb_hh[ej + 128];
    const float bE3 = eb_ih[ej + 192] + eb_hh[ej + 192];
    const int dr = tid >> 5, dv = tid & 31;   // dec elementwise: (row, unit), tid<128
    float bD0 = 0.f, bD1 = 0.f, bD2 = 0.f, bD3 = 0.f;
    if (tid < 128) {
        bD0 = db_ih[dv]      + db_hh[dv];
        bD1 = db_ih[dv + 32] + db_hh[dv + 32];
        bD2 = db_ih[dv + 64] + db_hh[dv + 64];
        bD3 = db_ih[dv + 96] + db_hh[dv + 96];
    }

    // ---- init xh state + x(0), prefetch x(1) ----
    for (int i = tid; i < 2 * ROWS * XHP; i += NTHR) sm[i] = 0.0f;
    __syncthreads();
    const int prow = (tid - 128) >> 5, pxj = (tid - 128) & 31;
    float x_pref = 0.0f;
    if (tid >= 128) {
        sm[OFF_XHE + prow * XHP + pxj] =
            x[((size_t)(b0 + prow) * T_STEPS + 0) * FDIM + pxj];
        x_pref = x[((size_t)(b0 + prow) * T_STEPS + 1) * FDIM + pxj];
    }
    __syncthreads();

    float c_enc = 0.0f, c_dec = 0.0f;
    const int peb = OFF_PE + e * 4 + q;   // partial write bases
    const int pdb = OFF_PD + e * 4 + q;

    for (int it = 0; it <= T_STEPS; ++it) {
        const bool do_enc = (it < T_STEPS);
        const bool do_dec = (it > 0);

        // ===== FMA phase: enc gates(it) + dec gates(it-1) =====
        if (do_enc) {
            #pragma unroll
            for (int r = 0; r < 4; ++r) {
                const ulonglong2* hp = reinterpret_cast<const ulonglong2*>(
                    sm + OFF_XHE + r * XHP + k0b);
                ull hv[12];
                #pragma unroll
                for (int c = 0; c < 6; ++c) {
                    ulonglong2 v = hp[c];
                    hv[2 * c] = v.x; hv[2 * c + 1] = v.y;
                }
                ull a0 = 0ull, a1 = 0ull, a2 = 0ull, a3 = 0ull;
                #pragma unroll
                for (int j = 0; j < 12; ++j) {
                    a0 = ffma2(wE[0][j], hv[j], a0);
                    a1 = ffma2(wE[1][j], hv[j], a1);
                    a2 = ffma2(wE[2][j], hv[j], a2);
                    a3 = ffma2(wE[3][j], hv[j], a3);
                }
                sm[peb + r * 1024 + 0]   = hsum2(a0);
                sm[peb + r * 1024 + 256] = hsum2(a1);
                sm[peb + r * 1024 + 512] = hsum2(a2);
                sm[peb + r * 1024 + 768] = hsum2(a3);
            }
        }
        if (do_dec) {
            #pragma unroll
            for (int r = 0; r < 4; ++r) {
                const ulonglong2* hp = reinterpret_cast<const ulonglong2*>(
                    sm + OFF_XHD + r * XHP + k0b);
                ull hv[12];
                #pragma unroll
                for (int c = 0; c < 6; ++c) {
                    ulonglong2 v = hp[c];
                    hv[2 * c] = v.x; hv[2 * c + 1] = v.y;
                }
                ull a0 = 0ull, a1 = 0ull;
                #pragma unroll
                for (int j = 0; j < 12; ++j) {
                    a0 = ffma2(wD[0][j], hv[j], a0);
                    a1 = ffma2(wD[1][j], hv[j], a1);
                }
                sm[pdb + r * 512 + 0]   = hsum2(a0);
                sm[pdb + r * 512 + 256] = hsum2(a1);
            }
        }
        __syncthreads();

        // ===== elementwise phase =====
        if (do_enc) {
            const float4* pe = reinterpret_cast<const float4*>(sm + OFF_PE)
                               + er * 256 + ej;
            float4 p0 = pe[0], p1 = pe[64], p2 = pe[128], p3 = pe[192];
            float g0 = sum4(p0) + bE0;
            float g1 = sum4(p1) + bE1;
            float g2 = sum4(p2) + bE2;
            float g3 = sum4(p3) + bE3;
            float iv = sigf(g0), fv = sigf(g1);
            float gv = tanh_fast(g2), ov = sigf(g3);
            c_enc = fv * c_enc + iv * gv;
            float h = ov * tanh_fast(c_enc);
            sm[OFF_XHE + er * XHP + FDIM + ej] = h;  // enc recurrence input
            sm[OFF_XHD + er * XHP + ej]        = h;  // dec input
        }
        if (do_dec && tid < 128) {
            const float4* pd = reinterpret_cast<const float4*>(sm + OFF_PD)
                               + dr * 128 + dv;
            float4 p0 = pd[0], p1 = pd[32], p2 = pd[64], p3 = pd[96];
            float g0 = sum4(p0) + bD0;
            float g1 = sum4(p1) + bD1;
            float g2 = sum4(p2) + bD2;
            float g3 = sum4(p3) + bD3;
            float iv = sigf(g0), fv = sigf(g1);
            float gv = tanh_fast(g2), ov = sigf(g3);
            c_dec = fv * c_dec + iv * gv;
            float h = ov * tanh_fast(c_dec);
            sm[OFF_XHD + dr * XHP + HDIM + dv] = h;  // dec recurrence input
            out[((size_t)(b0 + dr) * T_STEPS + (it - 1)) * FDIM + dv] = h;
        }
        if (tid >= 128) {
            if (it + 1 < T_STEPS)
                sm[OFF_XHE + prow * XHP + pxj] = x_pref;
            if (it + 2 < T_STEPS)
                x_pref = x[((size_t)(b0 + prow) * T_STEPS + (it + 2)) * FDIM + pxj];
        }
        __syncthreads();
    }
}

extern "C" void kernel_launch(void* const* d_in, const int* in_sizes, int n_in,
                              void* d_out, int out_size)
{
    (void)in_sizes; (void)n_in; (void)out_size;
    lstm_ae_kernel<<<NBLK, NTHR>>>(
        (const float*)d_in[0],
        (const float*)d_in[1], (const float*)d_in[2],
        (const float*)d_in[3], (const float*)d_in[4],
        (const float*)d_in[5], (const float*)d_in[6],
        (const float*)d_in[7], (const float*)d_in[8],
        (float*)d_out);
}

// round 3
// speedup vs baseline: 2.2454x; 1.0926x over previous
#include <cuda_runtime.h>

// LSTM autoencoder: enc (F=32 -> H=64), dec (H=64 -> F=32), B=512, T=1024.
// 128 blocks x 384 threads, 4 batch rows/block, one wave on 148 SMs.
// Thread (q = tid>>6 in [0,6), e = tid&63) owns k-share [16q, 16q+16) of:
//   enc gates {e, e+64, e+128, e+192} and dec gates {e, e+64}
// -> 96 weight floats/thread in 40 packed f32x2 regs. q is warp-uniform, so
// every hv LDS.128 is a pure broadcast (1 wavefront) and all partial STS/LDS
// are coalesced. 6 partials per gate reduced in the elementwise phase.
// Decoder runs one step behind the encoder: single FMA phase, 2 barriers/step.

#define T_STEPS 1024
#define FDIM    32
#define HDIM    64
#define ROWS    4
#define NBLK    128
#define NTHR    384
#define QN      6
#define SH      16     // k-share per thread
#define XHP     104    // padded xh row stride (floats)

// shared memory float offsets
#define OFF_XHE 0                         // [4][104]: x(32) | h_enc(64)
#define OFF_XHD (ROWS * XHP)              // [4][104]: h_enc(64) | h_dec(32)
#define OFF_PE  (2 * ROWS * XHP)          // [6][4][256] enc gate partials
#define OFF_PD  (OFF_PE + QN * ROWS * 256)// [6][4][128] dec gate partials
#define SMEMN   (OFF_PD + QN * ROWS * 128)// 10048 floats = 40192 B

typedef unsigned long long ull;
union U64F2 { ull u; float2 f; };

__device__ __forceinline__ ull pk(float lo, float hi) {
    U64F2 u; u.f = make_float2(lo, hi); return u.u;
}
__device__ __forceinline__ ull ffma2(ull a, ull b, ull c) {
    ull d;
    asm("fma.rn.f32x2 %0, %1, %2, %3;" : "=l"(d) : "l"(a), "l"(b), "l"(c));
    return d;
}
__device__ __forceinline__ float hsum2(ull a) {
    U64F2 u; u.u = a; return u.f.x + u.f.y;
}
__device__ __forceinline__ float sigf(float x) {
    return __fdividef(1.0f, 1.0f + __expf(-x));
}
__device__ __forceinline__ float tanh_fast(float x) {
    float e = __expf(2.0f * x);
    return 1.0f - __fdividef(2.0f, e + 1.0f);
}

__global__ void __launch_bounds__(NTHR, 1) lstm_ae_kernel(
    const float* __restrict__ x,
    const float* __restrict__ ew_ih, const float* __restrict__ ew_hh,
    const float* __restrict__ eb_ih, const float* __restrict__ eb_hh,
    const float* __restrict__ dw_ih, const float* __restrict__ dw_hh,
    const float* __restrict__ db_ih, const float* __restrict__ db_hh,
    float* __restrict__ out)
{
    __shared__ __align__(16) float sm[SMEMN];
    const int tid = threadIdx.x;
    const int b0  = blockIdx.x * ROWS;
    const int q   = tid >> 6;          // [0,6) warp-uniform
    const int e   = tid & 63;          // [0,64)
    const int kb  = SH * q;

    // ---- weights -> registers ----
    ull wE[4][8], wD[2][8];
    #pragma unroll
    for (int gi = 0; gi < 4; ++gi) {
        const int g = e + 64 * gi;
        #pragma unroll
        for (int j = 0; j < 8; ++j) {
            const int k0 = kb + 2 * j, k1 = k0 + 1;
            float lo = (k0 < FDIM) ? ew_ih[g * FDIM + k0] : ew_hh[g * HDIM + (k0 - FDIM)];
            float hi = (k1 < FDIM) ? ew_ih[g * FDIM + k1] : ew_hh[g * HDIM + (k1 - FDIM)];
            wE[gi][j] = pk(lo, hi);
        }
    }
    #pragma unroll
    for (int di = 0; di < 2; ++di) {
        const int g = e + 64 * di;
        #pragma unroll
        for (int j = 0; j < 8; ++j) {
            const int k0 = kb + 2 * j, k1 = k0 + 1;
            float lo = (k0 < HDIM) ? dw_ih[g * HDIM + k0] : dw_hh[g * FDIM + (k0 - HDIM)];
            float hi = (k1 < HDIM) ? dw_ih[g * HDIM + k1] : dw_hh[g * FDIM + (k1 - HDIM)];
            wD[di][j] = pk(lo, hi);
        }
    }

    // ---- elementwise-phase thread roles + biases ----
    const int er = tid >> 6, ej = tid & 63;        // enc ew (tid < 256)
    float bE0 = 0.f, bE1 = 0.f, bE2 = 0.f, bE3 = 0.f;
    if (tid < 256) {
        bE0 = eb_ih[ej]       + eb_hh[ej];
        bE1 = eb_ih[ej + 64]  + eb_hh[ej + 64];
        bE2 = eb_ih[ej + 128] + eb_hh[ej + 128];
        bE3 = eb_ih[ej + 192] + eb_hh[ej + 192];
    }
    const int dt = tid - 256;                      // dec ew / prefetch (tid >= 256)
    const int dr = dt >> 5, dv = dt & 31;
    float bD0 = 0.f, bD1 = 0.f, bD2 = 0.f, bD3 = 0.f;
    if (tid >= 256) {
        bD0 = db_ih[dv]      + db_hh[dv];
        bD1 = db_ih[dv + 32] + db_hh[dv + 32];
        bD2 = db_ih[dv + 64] + db_hh[dv + 64];
        bD3 = db_ih[dv + 96] + db_hh[dv + 96];
    }

    // ---- init xh state, x(0), prefetch x(1) ----
    for (int i = tid; i < 2 * ROWS * XHP; i += NTHR) sm[i] = 0.0f;
    __syncthreads();
    float x_pref = 0.0f;
    if (tid >= 256) {
        sm[OFF_XHE + dr * XHP + dv] =
            x[((size_t)(b0 + dr) * T_STEPS + 0) * FDIM + dv];
        x_pref = x[((size_t)(b0 + dr) * T_STEPS + 1) * FDIM + dv];
    }
    __syncthreads();

    float c_enc = 0.0f, c_dec = 0.0f;

    for (int it = 0; it <= T_STEPS; ++it) {
        // ===== FMA phase: enc gates(it) + dec gates(it-1) =====
        if (it < T_STEPS) {
            #pragma unroll
            for (int r = 0; r < 4; ++r) {
                const ulonglong2* hp = reinterpret_cast<const ulonglong2*>(
                    sm + OFF_XHE + r * XHP + kb);
                ulonglong2 v0 = hp[0], v1 = hp[1], v2 = hp[2], v3 = hp[3];
                ull hv[8] = {v0.x, v0.y, v1.x, v1.y, v2.x, v2.y, v3.x, v3.y};
                ull a0 = 0ull, a1 = 0ull, a2 = 0ull, a3 = 0ull;
                #pragma unroll
                for (int j = 0; j < 8; ++j) {
                    a0 = ffma2(wE[0][j], hv[j], a0);
                    a1 = ffma2(wE[1][j], hv[j], a1);
                    a2 = ffma2(wE[2][j], hv[j], a2);
                    a3 = ffma2(wE[3][j], hv[j], a3);
                }
                float* p = sm + OFF_PE + q * (ROWS * 256) + r * 256 + e;
                p[0]   = hsum2(a0);
                p[64]  = hsum2(a1);
                p[128] = hsum2(a2);
                p[192] = hsum2(a3);
            }
        }
        if (it > 0) {
            #pragma unroll
            for (int r = 0; r < 4; ++r) {
                const ulonglong2* hp = reinterpret_cast<const ulonglong2*>(
                    sm + OFF_XHD + r * XHP + kb);
                ulonglong2 v0 = hp[0], v1 = hp[1], v2 = hp[2], v3 = hp[3];
                ull hv[8] = {v0.x, v0.y, v1.x, v1.y, v2.x, v2.y, v3.x, v3.y};
                ull d0 = 0ull, d1 = 0ull;
                #pragma unroll
                for (int j = 0; j < 8; ++j) {
                    d0 = ffma2(wD[0][j], hv[j], d0);
                    d1 = ffma2(wD[1][j], hv[j], d1);
                }
                float* p = sm + OFF_PD + q * (ROWS * 128) + r * 128 + e;
                p[0]  = hsum2(d0);
                p[64] = hsum2(d1);
            }
        }
        __syncthreads();

        // ===== elementwise phase =====
        if (it < T_STEPS && tid < 256) {
            const float* p = sm + OFF_PE + er * 256 + ej;
            float g0 = bE0, g1 = bE1, g2 = bE2, g3 = bE3;
            #pragma unroll
            for (int qq = 0; qq < QN; ++qq) {
                const float* pq = p + qq * (ROWS * 256);
                g0 += pq[0];
                g1 += pq[64];
                g2 += pq[128];
                g3 += pq[192];
            }
            float iv = sigf(g0), fv = sigf(g1);
            float gv = tanh_fast(g2), ov = sigf(g3);
            c_enc = fv * c_enc + iv * gv;
            float h = ov * tanh_fast(c_enc);
            sm[OFF_XHE + er * XHP + FDIM + ej] = h;   // enc recurrence input
            sm[OFF_XHD + er * XHP + ej]        = h;   // dec input
        }
        if (tid >= 256) {
            if (it > 0) {
                const float* p = sm + OFF_PD + dr * 128 + dv;
                float g0 = bD0, g1 = bD1, g2 = bD2, g3 = bD3;
                #pragma unroll
                for (int qq = 0; qq < QN; ++qq) {
                    const float* pq = p + qq * (ROWS * 128);
                    g0 += pq[0];
                    g1 += pq[32];
                    g2 += pq[64];
                    g3 += pq[96];
                }
                float iv = sigf(g0), fv = sigf(g1);
                float gv = tanh_fast(g2), ov = sigf(g3);
                c_dec = fv * c_dec + iv * gv;
                float h = ov * tanh_fast(c_dec);
                sm[OFF_XHD + dr * XHP + HDIM + dv] = h;  // dec recurrence input
                out[((size_t)(b0 + dr) * T_STEPS + (it - 1)) * FDIM + dv] = h;
            }
            if (it + 1 < T_STEPS)
                sm[OFF_XHE + dr * XHP + dv] = x_pref;
            if (it + 2 < T_STEPS)
                x_pref = x[((size_t)(b0 + dr) * T_STEPS + (it + 2)) * FDIM + dv];
        }
        __syncthreads();
    }
}

extern "C" void kernel_launch(void* const* d_in, const int* in_sizes, int n_in,
                              void* d_out, int out_size)
{
    (void)in_sizes; (void)n_in; (void)out_size;
    lstm_ae_kernel<<<NBLK, NTHR>>>(
        (const float*)d_in[0],
        (const float*)d_in[1], (const float*)d_in[2],
        (const float*)d_in[3], (const float*)d_in[4],
        (const float*)d_in[5], (const float*)d_in[6],
        (const float*)d_in[7], (const float*)d_in[8],
        (float*)d_out);
}

// round 4
// speedup vs baseline: 2.5493x; 1.1353x over previous
#include <cuda_runtime.h>

// LSTM autoencoder: enc (F=32 -> H=64), dec (H=64 -> F=32), B=512, T=1024.
// 128 blocks x 384 threads, 4 batch rows/block.
// Quad-per-unit layout: tid>>2 = unit (0..63 enc, 64..95 dec),
//   bit1 of tid = gate pair p (0:(i,f), 1:(g,o)), bit0 = k-half h (48 of 96).
// Each thread: 2 gates x 48 k-floats in regs (96 floats), x 4 rows = 192 FFMA2.
// Gate reduction via 6 shfl.bfly (no SMEM partials, no extra barrier).
// Elementwise: thread handles (unit, row = tid&3), c in one register.
// xh state double-buffered -> ONE __syncthreads per step. Decoder lags 1 step.

#define T_STEPS 1024
#define FDIM    32
#define HDIM    64
#define ROWS    4
#define NBLK    128
#define NTHR    384
#define XHP     104

// SMEM: XHE[2][4][XHP] (x | h_enc), XHD[2][4][XHP] (h_enc | h_dec)
#define OFF_XHE(b) ((b) * (ROWS * XHP))
#define OFF_XHD(b) (2 * ROWS * XHP + (b) * (ROWS * XHP))
#define SMEMN      (4 * ROWS * XHP)

typedef unsigned long long ull;
union U64F2 { ull u; float2 f; };

__device__ __forceinline__ ull pk(float lo, float hi) {
    U64F2 u; u.f = make_float2(lo, hi); return u.u;
}
__device__ __forceinline__ ull ffma2(ull a, ull b, ull c) {
    ull d;
    asm("fma.rn.f32x2 %0, %1, %2, %3;" : "=l"(d) : "l"(a), "l"(b), "l"(c));
    return d;
}
__device__ __forceinline__ float hsum2(ull a) {
    U64F2 u; u.u = a; return u.f.x + u.f.y;
}
__device__ __forceinline__ float sigf(float x) {
    return __fdividef(1.0f, 1.0f + __expf(-x));
}
__device__ __forceinline__ float tanh_fast(float x) {
    float e = __expf(2.0f * x);
    return 1.0f - __fdividef(2.0f, e + 1.0f);
}
// select s[idx] from 4 scalars (idx runtime 0..3) without local memory
__device__ __forceinline__ float pick4(float v0, float v1, float v2, float v3, int idx) {
    float a = (idx & 1) ? v1 : v0;
    float b = (idx & 1) ? v3 : v2;
    return (idx & 2) ? b : a;
}

__global__ void __launch_bounds__(NTHR, 1) lstm_ae_kernel(
    const float* __restrict__ x,
    const float* __restrict__ ew_ih, const float* __restrict__ ew_hh,
    const float* __restrict__ eb_ih, const float* __restrict__ eb_hh,
    const float* __restrict__ dw_ih, const float* __restrict__ dw_hh,
    const float* __restrict__ db_ih, const float* __restrict__ db_hh,
    float* __restrict__ out)
{
    __shared__ __align__(16) float sm[SMEMN];
    const int tid = threadIdx.x;
    const int b0  = blockIdx.x * ROWS;

    const int ug   = tid >> 2;              // global unit 0..95
    const bool dec = (ug >= 64);
    const int u    = dec ? (ug - 64) : ug;  // unit within its lstm
    const int p    = (tid >> 1) & 1;        // gate pair
    const int h    = tid & 1;               // k-half
    const int rr   = tid & 3;               // elementwise row for this thread
    const int kb   = 48 * h;

    // ---- weights -> registers: 2 gates x 48 floats (24 packed f32x2 each) ----
    ull wA[24], wB[24];
    {
        const int U  = dec ? FDIM : HDIM;         // units in this lstm
        const int gA = u + (p ? 2 * U : 0);       // i or g
        const int gB = gA + U;                    // f or o
        const int KI = dec ? HDIM : FDIM;         // w_ih input width
        const float* wih = dec ? dw_ih : ew_ih;
        const float* whh = dec ? dw_hh : ew_hh;
        const int KH = dec ? FDIM : HDIM;         // w_hh input width
        #pragma unroll
        for (int j = 0; j < 24; ++j) {
            const int k0 = kb + 2 * j, k1 = k0 + 1;
            float a0 = (k0 < KI) ? wih[gA * KI + k0] : whh[gA * KH + (k0 - KI)];
            float a1 = (k1 < KI) ? wih[gA * KI + k1] : whh[gA * KH + (k1 - KI)];
            float b0v = (k0 < KI) ? wih[gB * KI + k0] : whh[gB * KH + (k0 - KI)];
            float b1v = (k1 < KI) ? wih[gB * KI + k1] : whh[gB * KH + (k1 - KI)];
            wA[j] = pk(a0, a1);
            wB[j] = pk(b0v, b1v);
        }
    }

    // ---- biases for this unit's i,f,g,o ----
    const int U2 = dec ? FDIM : HDIM;
    const float* bih = dec ? db_ih : eb_ih;
    const float* bhh = dec ? db_hh : eb_hh;
    const float bi = bih[u]          + bhh[u];
    const float bf = bih[u + U2]     + bhh[u + U2];
    const float bg = bih[u + 2 * U2] + bhh[u + 2 * U2];
    const float bo = bih[u + 3 * U2] + bhh[u + 3 * U2];

    // ---- init state ----
    for (int i = tid; i < SMEMN; i += NTHR) sm[i] = 0.0f;
    __syncthreads();
    float x_pref = 0.0f;
    if (dec) {  // dec threads cover (rr, u) = 4 x 32 x-slots
        sm[OFF_XHE(0) + rr * XHP + u] =
            x[((size_t)(b0 + rr) * T_STEPS + 0) * FDIM + u];
        x_pref = x[((size_t)(b0 + rr) * T_STEPS + 1) * FDIM + u];
    }
    __syncthreads();

    float c_st = 0.0f;   // c for (unit u, row rr): enc state, or dec state

    for (int it = 0; it <= T_STEPS; ++it) {
        const int rb = it & 1, wb = rb ^ 1;
        const float* xh = sm + (dec ? OFF_XHD(rb) : OFF_XHE(rb));

        // ===== FMA: 2 gates x 4 rows over this thread's k-half =====
        float sA0, sA1, sA2, sA3, sB0, sB1, sB2, sB3;
        #pragma unroll
        for (int r = 0; r < 4; ++r) {
            const ulonglong2* hp =
                reinterpret_cast<const ulonglong2*>(xh + r * XHP + kb);
            ull aA = 0ull, aB = 0ull;
            #pragma unroll
            for (int c = 0; c < 12; ++c) {
                ulonglong2 v = hp[c];
                aA = ffma2(wA[2 * c],     v.x, aA);
                aA = ffma2(wA[2 * c + 1], v.y, aA);
                aB = ffma2(wB[2 * c],     v.x, aB);
                aB = ffma2(wB[2 * c + 1], v.y, aB);
            }
            float fa = hsum2(aA), fb = hsum2(aB);
            if (r == 0) { sA0 = fa; sB0 = fb; }
            else if (r == 1) { sA1 = fa; sB1 = fb; }
            else if (r == 2) { sA2 = fa; sB2 = fb; }
            else { sA3 = fa; sB3 = fb; }
        }

        // ===== quad reduction: 6 shfl.bfly =====
        // k-half combine for rows rr and rr^2 (send the row the partner needs)
        float myA = pick4(sA0, sA1, sA2, sA3, rr) +
                    __shfl_xor_sync(0xFFFFFFFFu, pick4(sA0, sA1, sA2, sA3, rr ^ 1), 1);
        float myB = pick4(sB0, sB1, sB2, sB3, rr) +
                    __shfl_xor_sync(0xFFFFFFFFu, pick4(sB0, sB1, sB2, sB3, rr ^ 1), 1);
        float otA = pick4(sA0, sA1, sA2, sA3, rr ^ 2) +
                    __shfl_xor_sync(0xFFFFFFFFu, pick4(sA0, sA1, sA2, sA3, rr ^ 3), 1);
        float otB = pick4(sB0, sB1, sB2, sB3, rr ^ 2) +
                    __shfl_xor_sync(0xFFFFFFFFu, pick4(sB0, sB1, sB2, sB3, rr ^ 3), 1);
        // gate-pair exchange: receive partner's gates for my row
        float pA = __shfl_xor_sync(0xFFFFFFFFu, otA, 2);
        float pB = __shfl_xor_sync(0xFFFFFFFFu, otB, 2);

        float gi = (p ? pA : myA) + bi;
        float gf = (p ? pB : myB) + bf;
        float gg = (p ? myA : pA) + bg;
        float go = (p ? myB : pB) + bo;

        // ===== elementwise + state/stores =====
        if (!dec) {
            if (it < T_STEPS) {
                float iv = sigf(gi), fv = sigf(gf);
                float gv = tanh_fast(gg), ov = sigf(go);
                c_st = fv * c_st + iv * gv;
                float hv = ov * tanh_fast(c_st);
                sm[OFF_XHE(wb) + rr * XHP + FDIM + u] = hv;  // enc recurrence
                sm[OFF_XHD(wb) + rr * XHP + u]        = hv;  // dec input
            }
        } else {
            if (it > 0) {
                float iv = sigf(gi), fv = sigf(gf);
                float gv = tanh_fast(gg), ov = sigf(go);
                c_st = fv * c_st + iv * gv;
                float hv = ov * tanh_fast(c_st);
                sm[OFF_XHD(wb) + rr * XHP + HDIM + u] = hv;  // dec recurrence
                out[((size_t)(b0 + rr) * T_STEPS + (it - 1)) * FDIM + u] = hv;
            }
            // x pipeline: write x(it+1) into next buffer, prefetch x(it+2)
            if (it + 1 < T_STEPS)
                sm[OFF_XHE(wb) + rr * XHP + u] = x_pref;
            if (it + 2 < T_STEPS)
                x_pref = x[((size_t)(b0 + rr) * T_STEPS + (it + 2)) * FDIM + u];
        }
        __syncthreads();
    }
}

extern "C" void kernel_launch(void* const* d_in, const int* in_sizes, int n_in,
                              void* d_out, int out_size)
{
    (void)in_sizes; (void)n_in; (void)out_size;
    lstm_ae_kernel<<<NBLK, NTHR>>>(
        (const float*)d_in[0],
        (const float*)d_in[1], (const float*)d_in[2],
        (const float*)d_in[3], (const float*)d_in[4],
        (const float*)d_in[5], (const float*)d_in[6],
        (const float*)d_in[7], (const float*)d_in[8],
        (float*)d_out);
}